// round 11
// baseline (speedup 1.0000x reference)
#include <cuda_runtime.h>
#include <math.h>

// ---------------- problem constants ----------------
#define BB     16
#define F1N    16
#define CC     64
#define TTOT   1000
#define KK     64
#define C2N    32
#define PWN    16
#define EPSF   1e-5f

// ---------------- kernel-1 tiling ----------------
#define TILE   112         // time points per block
#define NTILE  9           // 9*112 = 1008 >= 1000 (last tile partial)
#define TSUB   16          // chunk of t per phase round
#define NCHUNK 7           // 7*16 = 112
#define XP_W   91          // x pairs per row (odd 8B stride -> conflict-free)
#define ES_S   18          // es row stride (even -> aligned STS.64)

// smem float counts (order matters; all offsets 16B-aligned where needed)
#define NF_XE   (CC*XP_W*2)     // 11648
#define NF_XO   (CC*XP_W*2)     // 11648
#define NF_WSD  (F1N*KK*2)      // 2048 (dup-pair weights)
#define NF_AH   (CC*CC)         // 4096
#define NF_DW   (C2N*CC)        // 2048
#define NF_ES   (F1N*CC*ES_S)   // 18432
#define NF_XG   (CC*TSUB)       // 1024
#define NF_M0   (C2N*CC)        // 2048
#define NF_PS   (C2N*TSUB)      // 512
#define NF_SMALL 144
#define SMEM_FLOATS (NF_XE+NF_XO+NF_WSD+NF_AH+NF_DW+NF_ES+NF_XG+NF_M0+NF_PS+NF_SMALL)
#define SMEM_BYTES  (SMEM_FLOATS*4)   // ~215 KB

// K2 tiling
#define K2B_W    8
#define K2B_T    (K2B_W*PWN)  // 128
#define NTILE2   8
#define NPOOL    62

__device__ float g_h2[BB * C2N * TTOT];
__device__ float g_psum[BB * C2N * NTILE];
__device__ float g_pmax[BB * C2N * NTILE];
__device__ float g_q[BB * C2N * NPOOL];

typedef unsigned long long ull;

__device__ __forceinline__ float eluf(float v) { return v > 0.f ? v : expm1f(v); }
__device__ __forceinline__ float sigmf(float z) { return 1.f / (1.f + expf(-z)); }

__device__ __forceinline__ ull fma2(ull a, ull b, ull c) {
    ull d;
    asm("fma.rn.f32x2 %0, %1, %2, %3;" : "=l"(d) : "l"(a), "l"(b), "l"(c));
    return d;
}
__device__ __forceinline__ ull pack2(float lo, float hi) {
    ull d;
    asm("mov.b64 %0, {%1, %2};" : "=l"(d) : "f"(lo), "f"(hi));
    return d;
}
__device__ __forceinline__ void unpack2(ull v, float& lo, float& hi) {
    asm("mov.b64 {%0, %1}, %2;" : "=f"(lo), "=f"(hi) : "l"(v));
}

// ============================================================
// Kernel 1: temporal conv (FFMA2, even/odd tap passes) + BN1 +
//  ELU + GCN residual + expansion + BN2 -> g_h2 (+ stats)
// grid (NTILE, BB) = 144 blocks, 1024 threads
// ============================================================
__global__ void __launch_bounds__(1024, 1)
k1_front(const float* __restrict__ x,
         const float* __restrict__ ahat_g,
         const float* __restrict__ w1,  const float* __restrict__ b1c,
         const float* __restrict__ g1,  const float* __restrict__ bb1,
         const float* __restrict__ m1,  const float* __restrict__ v1,
         const float* __restrict__ gcw, const float* __restrict__ gcb,
         const float* __restrict__ dww_g, const float* __restrict__ dwb,
         const float* __restrict__ g2,  const float* __restrict__ bb2,
         const float* __restrict__ m2,  const float* __restrict__ v2)
{
    extern __shared__ float sm[];
    float* xe  = sm;                 // [CC][XP_W] pairs (x[2i],x[2i+1])
    float* xo  = xe  + NF_XE;        // [CC][XP_W] pairs (x[2i+1],x[2i+2])
    float* wsd = xo  + NF_XO;        // [F1][KK] dup pairs (w,w)
    float* ah  = wsd + NF_WSD;       // [CC][CC]
    float* dw  = ah  + NF_AH;        // [C2][CC]
    float* es  = dw  + NF_DW;        // [F1][CC][ES_S]
    float* xg  = es  + NF_ES;        // [CC][TSUB]
    float* m0  = xg  + NF_XG;        // [C2][CC]
    float* ps  = m0  + NF_M0;        // [C2][TSUB]
    float* o1s = ps  + NF_PS;        // [F1]
    float* gw  = o1s + F1N;          // [F1]
    float* s2  = gw  + F1N;          // [C2]
    float* sh2 = s2  + C2N;          // [C2]
    float* cst = sh2 + C2N;          // [C2]

    const int tid = threadIdx.x;
    const int b   = blockIdx.y;
    const int t0  = blockIdx.x * TILE;

    // ---- load x as pair arrays (rel index j: x[t0-31+j]) ----
    for (int idx = tid; idx < CC * XP_W; idx += 1024) {
        int c = idx / XP_W, i = idx % XP_W;
        int tg0 = t0 - 31 + 2 * i;
        const float* xr = x + (b * CC + c) * TTOT;
        float v0 = (tg0 >= 0     && tg0 < TTOT)     ? xr[tg0]     : 0.f;
        float v1 = (tg0 + 1 >= 0 && tg0 + 1 < TTOT) ? xr[tg0 + 1] : 0.f;
        float v2 = (tg0 + 2 >= 0 && tg0 + 2 < TTOT) ? xr[tg0 + 2] : 0.f;
        ((float2*)xe)[c * XP_W + i] = make_float2(v0, v1);
        ((float2*)xo)[c * XP_W + i] = make_float2(v1, v2);
    }
    for (int i = tid; i < F1N * KK; i += 1024) {
        int f = i / KK;
        float s1 = g1[f] * rsqrtf(v1[f] + EPSF);
        float w = w1[i] * s1;
        ((float2*)wsd)[i] = make_float2(w, w);
    }
    for (int i = tid; i < NF_AH; i += 1024) ah[i] = ahat_g[i];
    for (int i = tid; i < NF_DW; i += 1024) dw[i] = dww_g[i];
    if (tid < F1N) {
        float s1 = g1[tid] * rsqrtf(v1[tid] + EPSF);
        o1s[tid] = b1c[tid] * s1 + bb1[tid] - m1[tid] * s1;
        gw[tid]  = gcw[tid];
    }
    if (tid < C2N) {
        float s = g2[tid] * rsqrtf(v2[tid] + EPSF);
        s2[tid]  = s;
        sh2[tid] = bb2[tid] - m2[tid] * s;
    }
    __syncthreads();
    if (tid < C2N) {
        float wsum = 0.f;
        for (int c = 0; c < CC; ++c) wsum += dw[tid * CC + c];
        cst[tid] = gcb[tid >> 1] * wsum + dwb[tid];
    }
    // ---- precompute M0 = (gw/F1) * dw @ ahat ----
    for (int it = tid; it < C2N * CC; it += 1024) {
        int c2 = it >> 6, j = it & 63;
        const float* dr = dw + c2 * CC;
        float s = 0.f;
        #pragma unroll 8
        for (int cc = 0; cc < CC; ++cc)
            s = fmaf(dr[cc], ah[cc * CC + j], s);
        m0[it] = s * gw[c2 >> 1] * (1.f / F1N);
    }
    __syncthreads();

    // conv thread map: (f, c)
    const int f = tid >> 6;           // 0..15
    const int c = tid & 63;
    const ull* xer = (const ull*)xe + c * XP_W;
    const ull* xor_ = (const ull*)xo + c * XP_W;
    const ull* wrow = (const ull*)wsd + f * KK;
    ull* e8 = (ull*)es + (f * CC + c) * (ES_S / 2);
    const float o1 = o1s[f];

    float stat_s = 0.f, stat_m = -INFINITY;

    for (int chk = 0; chk < NCHUNK; ++chk) {
        const int cb = chk * (TSUB / 2);   // pair base

        // ---- phase A: conv via FFMA2, even then odd taps ----
        {
            ull acc[8];
            #pragma unroll
            for (int m = 0; m < 8; ++m) acc[m] = 0ull;

            // even taps k=2p: pairs from XE
            {
                ull win[8];
                #pragma unroll
                for (int m = 0; m < 8; ++m) win[m] = xer[cb + m];
                #pragma unroll 1
                for (int g = 0; g < 4; ++g) {
                    const int pb = g * 8;
                    #pragma unroll
                    for (int pp = 0; pp < 8; ++pp) {
                        ull w2 = wrow[2 * (pb + pp)];
                        #pragma unroll
                        for (int m = 0; m < 8; ++m)
                            acc[m] = fma2(w2, win[(pp + m) & 7], acc[m]);
                        win[pp] = xer[cb + pb + pp + 8];
                    }
                }
            }
            // odd taps k=2p+1: pairs from XO
            {
                ull win[8];
                #pragma unroll
                for (int m = 0; m < 8; ++m) win[m] = xor_[cb + m];
                #pragma unroll 1
                for (int g = 0; g < 4; ++g) {
                    const int pb = g * 8;
                    #pragma unroll
                    for (int pp = 0; pp < 8; ++pp) {
                        ull w2 = wrow[2 * (pb + pp) + 1];
                        #pragma unroll
                        for (int m = 0; m < 8; ++m)
                            acc[m] = fma2(w2, win[(pp + m) & 7], acc[m]);
                        win[pp] = xor_[cb + pb + pp + 8];
                    }
                }
            }
            #pragma unroll
            for (int m = 0; m < 8; ++m) {
                float lo, hi;
                unpack2(acc[m], lo, hi);
                e8[m] = pack2(eluf(lo + o1), eluf(hi + o1));
            }
        }
        __syncthreads();

        // ---- phase 2 (split block):
        //      lower 512: ps[c2,tt] = Sum_cc dw[c2,cc]*es[f,cc,tt]
        //      upper 512: xg[cc,tt] = Sum_f es[f,cc,tt] (2 items)
        if (tid < C2N * TSUB) {
            int c2 = tid >> 4, tt = tid & 15;
            int ff = c2 >> 1;
            const float4* dr4 = (const float4*)(dw + c2 * CC);
            const float* er = es + ff * CC * ES_S + tt;
            float s = 0.f;
            #pragma unroll
            for (int q = 0; q < 16; ++q) {
                float4 d = dr4[q];
                int cc = q * 4;
                s = fmaf(d.x, er[(cc + 0) * ES_S], s);
                s = fmaf(d.y, er[(cc + 1) * ES_S], s);
                s = fmaf(d.z, er[(cc + 2) * ES_S], s);
                s = fmaf(d.w, er[(cc + 3) * ES_S], s);
            }
            ps[tid] = s;
        } else {
            int base = tid - 512;
            #pragma unroll
            for (int r = 0; r < 2; ++r) {
                int item = base + r * 512;
                int cc = item >> 4, tt = item & 15;
                const float* er = es + cc * ES_S + tt;
                float s = 0.f;
                #pragma unroll
                for (int ff = 0; ff < F1N; ++ff)
                    s += er[ff * CC * ES_S];
                xg[item] = s;
            }
        }
        __syncthreads();

        // ---- phase 3: combine + BN2 -> g_h2 + fused stats ----
        if (tid < C2N * TSUB) {
            int c2 = tid >> 4, tt = tid & 15;
            const float4* mr4 = (const float4*)(m0 + c2 * CC);
            const float* xr = xg + tt;
            float s = ps[tid];
            #pragma unroll
            for (int q = 0; q < 16; ++q) {
                float4 m = mr4[q];
                int j = q * 4;
                s = fmaf(m.x, xr[(j + 0) * TSUB], s);
                s = fmaf(m.y, xr[(j + 1) * TSUB], s);
                s = fmaf(m.z, xr[(j + 2) * TSUB], s);
                s = fmaf(m.w, xr[(j + 3) * TSUB], s);
            }
            float outv = (s + cst[c2]) * s2[c2] + sh2[c2];
            int t = t0 + chk * TSUB + tt;
            bool valid = (t < TTOT);
            if (valid) g_h2[(b * C2N + c2) * TTOT + t] = outv;
            float sv = valid ? outv : 0.f;
            float mv = valid ? outv : -INFINITY;
            #pragma unroll
            for (int o = 8; o > 0; o >>= 1) {
                sv += __shfl_down_sync(0xffffffffu, sv, o, 16);
                mv  = fmaxf(mv, __shfl_down_sync(0xffffffffu, mv, o, 16));
            }
            if (tt == 0) { stat_s += sv; stat_m = fmaxf(stat_m, mv); }
        }
        __syncthreads();
    }

    if (tid < C2N * TSUB && (tid & 15) == 0) {
        int c2 = tid >> 4;
        g_psum[(b * C2N + c2) * NTILE + blockIdx.x] = stat_s;
        g_pmax[(b * C2N + c2) * NTILE + blockIdx.x] = stat_m;
    }
}

// ============================================================
// Kernel 2b: channel attn + spatial attn + ELU + pool16 -> g_q
// ============================================================
#define H2S_S 131
__global__ void __launch_bounds__(256, 4)
k2b_attpool(const float* __restrict__ caw1, const float* __restrict__ cab1,
            const float* __restrict__ caw2, const float* __restrict__ cab2,
            const float* __restrict__ saw,
            const float* __restrict__ sag, const float* __restrict__ sab,
            const float* __restrict__ sam, const float* __restrict__ sav)
{
    __shared__ float att[C2N];
    __shared__ float h2s[C2N * H2S_S];
    __shared__ float mms[K2B_T + 2], mxs[K2B_T + 2], sgs[K2B_T];
    __shared__ float sstat[C2N];

    const int tile = blockIdx.x, b = blockIdx.y;
    const int tid  = threadIdx.x;
    const int t0   = tile * K2B_T;
    const int tw   = (tile == NTILE2 - 1) ? (NPOOL * PWN - t0) : K2B_T;
    const int nw   = tw / PWN;

    if (tid < C2N) {
        float s = 0.f, m = -INFINITY;
        const float* pss = g_psum + (b * C2N + tid) * NTILE;
        const float* pm = g_pmax + (b * C2N + tid) * NTILE;
        #pragma unroll
        for (int tl = 0; tl < NTILE; ++tl) {
            s += pss[tl]; m = fmaxf(m, pm[tl]);
        }
        sstat[tid] = s * (1.f / TTOT) + m;
    }
    __syncthreads();
    if (tid < C2N) {
        float r0 = cab1[0], r1 = cab1[1];
        for (int j = 0; j < C2N; ++j) {
            r0 += caw1[j] * sstat[j];
            r1 += caw1[C2N + j] * sstat[j];
        }
        r0 = fmaxf(r0, 0.f); r1 = fmaxf(r1, 0.f);
        att[tid] = sigmf(cab2[tid] + caw2[tid * 2] * r0 + caw2[tid * 2 + 1] * r1);
    }
    __syncthreads();

    const float* h2 = g_h2 + b * C2N * TTOT;
    for (int idx = tid; idx < C2N * (tw + 2); idx += 256) {
        int c2 = idx / (tw + 2), j = idx % (tw + 2);
        int t = t0 - 1 + j;
        float v = (t >= 0 && t < TTOT) ? h2[c2 * TTOT + t] * att[c2] : 0.f;
        h2s[c2 * H2S_S + j] = v;
    }
    __syncthreads();

    for (int j = tid; j < tw + 2; j += 256) {
        float s = 0.f, mx = -INFINITY;
        #pragma unroll 8
        for (int c2 = 0; c2 < C2N; ++c2) {
            float v = h2s[c2 * H2S_S + j];
            s += v; mx = fmaxf(mx, v);
        }
        mms[j] = s * (1.f / C2N);
        mxs[j] = mx;
    }
    __syncthreads();

    {
        float ssa = sag[0] * rsqrtf(sav[0] + EPSF);
        float sha = sab[0] - sam[0] * ssa;
        for (int j = tid; j < tw; j += 256) {
            int t = t0 + j;
            float acc = 0.f;
            #pragma unroll
            for (int kw = 0; kw < 3; ++kw) {
                int tt = t - 1 + kw;
                if (tt >= 0 && tt < TTOT)
                    acc += saw[3 + kw] * mms[j + kw] + saw[12 + kw] * mxs[j + kw];
            }
            sgs[j] = sigmf(acc * ssa + sha);
        }
    }
    __syncthreads();

    {
        int c2 = tid & 31, w = tid >> 5;
        if (w < nw) {
            float acc = 0.f;
            #pragma unroll
            for (int j = 0; j < PWN; ++j) {
                int tl = w * PWN + j;
                acc += eluf(h2s[c2 * H2S_S + tl + 1] * sgs[tl]);
            }
            g_q[(b * C2N + c2) * NPOOL + tile * K2B_W + w] = acc * (1.f / PWN);
        }
    }
}

// ============================================================
// Kernel 2c: depthwise sep conv + BN3 + ELU + pool16 -> out
// ============================================================
__global__ void __launch_bounds__(256, 4)
k2c_tail(const float* __restrict__ sepw, const float* __restrict__ sepb,
         const float* __restrict__ g3, const float* __restrict__ bb3,
         const float* __restrict__ m3, const float* __restrict__ v3,
         float* __restrict__ out)
{
    __shared__ float qs[C2N * NPOOL];
    __shared__ float sw[C2N * PWN];
    const int b = blockIdx.x, tid = threadIdx.x;
    for (int i = tid; i < C2N * NPOOL; i += 256)
        qs[i] = g_q[b * C2N * NPOOL + i];
    for (int i = tid; i < C2N * PWN; i += 256)
        sw[i] = sepw[i];
    __syncthreads();

    const int j  = tid & 15;
    const int e0 = tid >> 4;
    for (int r = 0; r < 6; ++r) {
        int e  = e0 + r * 16;          // 0..95 = c2*3 + to
        int c2 = e / 3, to = e % 3;
        int t  = to * PWN + j;
        float y = sepb[c2];
        #pragma unroll
        for (int u = 0; u < PWN; ++u) {
            int tq = t - 7 + u;
            if (tq >= 0 && tq < NPOOL) y = fmaf(sw[c2 * PWN + u], qs[c2 * NPOOL + tq], y);
        }
        float s3  = g3[c2] * rsqrtf(v3[c2] + EPSF);
        float sh3 = bb3[c2] - m3[c2] * s3;
        float v = eluf(y * s3 + sh3);
        #pragma unroll
        for (int o = 8; o > 0; o >>= 1)
            v += __shfl_down_sync(0xffffffffu, v, o, 16);
        if (j == 0) out[b * (C2N * 3) + e] = v * (1.f / PWN);
    }
}

// ============================================================
extern "C" void kernel_launch(void* const* d_in, const int* in_sizes, int n_in,
                              void* d_out, int out_size)
{
    const float* x     = (const float*)d_in[0];
    const float* ahat  = (const float*)d_in[1];
    const float* w1    = (const float*)d_in[2];
    const float* b1c   = (const float*)d_in[3];
    const float* g1    = (const float*)d_in[4];
    const float* bb1   = (const float*)d_in[5];
    const float* m1    = (const float*)d_in[6];
    const float* v1    = (const float*)d_in[7];
    const float* gcw   = (const float*)d_in[8];
    const float* gcb   = (const float*)d_in[9];
    const float* dww   = (const float*)d_in[10];
    const float* dwb   = (const float*)d_in[11];
    const float* g2    = (const float*)d_in[12];
    const float* bb2   = (const float*)d_in[13];
    const float* m2    = (const float*)d_in[14];
    const float* v2    = (const float*)d_in[15];
    const float* caw1  = (const float*)d_in[16];
    const float* cab1  = (const float*)d_in[17];
    const float* caw2  = (const float*)d_in[18];
    const float* cab2  = (const float*)d_in[19];
    const float* saw   = (const float*)d_in[20];
    const float* sag   = (const float*)d_in[21];
    const float* sab   = (const float*)d_in[22];
    const float* sam   = (const float*)d_in[23];
    const float* sav   = (const float*)d_in[24];
    const float* sepw  = (const float*)d_in[25];
    const float* sepb  = (const float*)d_in[26];
    const float* g3    = (const float*)d_in[27];
    const float* bb3   = (const float*)d_in[28];
    const float* m3    = (const float*)d_in[29];
    const float* v3    = (const float*)d_in[30];

    cudaFuncSetAttribute(k1_front, cudaFuncAttributeMaxDynamicSharedMemorySize,
                         SMEM_BYTES);

    dim3 grid1(NTILE, BB);
    k1_front<<<grid1, 1024, SMEM_BYTES>>>(x, ahat, w1, b1c, g1, bb1, m1, v1,
                                          gcw, gcb, dww, dwb, g2, bb2, m2, v2);

    dim3 grid2b(NTILE2, BB);
    k2b_attpool<<<grid2b, 256>>>(caw1, cab1, caw2, cab2, saw, sag, sab, sam, sav);

    k2c_tail<<<BB, 256>>>(sepw, sepb, g3, bb3, m3, v3, (float*)d_out);
}

// round 12
// speedup vs baseline: 1.0922x; 1.0922x over previous
#include <cuda_runtime.h>
#include <math.h>

// ---------------- problem constants ----------------
#define BB     16
#define F1N    16
#define CC     64
#define TTOT   1000
#define KK     64
#define C2N    32
#define PWN    16
#define EPSF   1e-5f

// ---------------- kernel-1 tiling ----------------
#define TILE   112         // time points per block
#define NTILE  9           // 9*112 = 1008 >= 1000 (last tile partial)
#define TSUB   16          // chunk of t per phase round
#define NCHUNK 7           // 7*16 = 112
#define XS_W   177         // TILE + 63 halo + 2 (odd -> conflict-free)
#define ES_S   17          // es row stride (odd -> conflict-free)

// smem float counts
#define NF_XS   (CC*XS_W)       // 11328
#define NF_WS   (F1N*KK)        // 1024
#define NF_AH   (CC*CC)         // 4096
#define NF_DW   (C2N*CC)        // 2048
#define NF_ES1  (F1N*CC*ES_S)   // 17408 (one buffer)
#define NF_XG   (CC*TSUB)       // 1024
#define NF_M0   (C2N*CC)        // 2048
#define NF_PS   (C2N*TSUB)      // 512
#define NF_SMALL 144
#define SMEM_FLOATS (NF_XS+NF_WS+NF_AH+NF_DW+2*NF_ES1+NF_XG+NF_M0+NF_PS+NF_SMALL)
#define SMEM_BYTES  (SMEM_FLOATS*4)   // 228160 B <= 232448 cap

// K2 tiling
#define K2B_W    8
#define K2B_T    (K2B_W*PWN)  // 128
#define NTILE2   8
#define NPOOL    62

__device__ float g_h2[BB * C2N * TTOT];
__device__ float g_psum[BB * C2N * NTILE];
__device__ float g_pmax[BB * C2N * NTILE];
__device__ float g_q[BB * C2N * NPOOL];

__device__ __forceinline__ float eluf(float v) { return v > 0.f ? v : expm1f(v); }
__device__ __forceinline__ float sigmf(float z) { return 1.f / (1.f + expf(-z)); }

#define BAR_SYNC(id, cnt)   asm volatile("bar.sync %0, %1;"   :: "r"(id), "r"(cnt) : "memory")
#define BAR_ARRIVE(id, cnt) asm volatile("bar.arrive %0, %1;" :: "r"(id), "r"(cnt) : "memory")

// ============================================================
// Kernel 1: warp-specialized producer/consumer.
//  warps 0-15 : temporal conv + BN1 + ELU -> es[p] (double buffer)
//  warps 16-31: GCN/expansion/BN2 -> g_h2 + stats
// grid (NTILE, BB) = 144 blocks, 1024 threads
// ============================================================
__global__ void __launch_bounds__(1024, 1)
k1_front(const float* __restrict__ x,
         const float* __restrict__ ahat_g,
         const float* __restrict__ w1,  const float* __restrict__ b1c,
         const float* __restrict__ g1,  const float* __restrict__ bb1,
         const float* __restrict__ m1,  const float* __restrict__ v1,
         const float* __restrict__ gcw, const float* __restrict__ gcb,
         const float* __restrict__ dww_g, const float* __restrict__ dwb,
         const float* __restrict__ g2,  const float* __restrict__ bb2,
         const float* __restrict__ m2,  const float* __restrict__ v2)
{
    extern __shared__ float sm[];
    float* xs  = sm;                 // [CC][XS_W]
    float* ws  = xs  + NF_XS;        // [F1][KK] (BN1-scaled weights)
    float* ah  = ws  + NF_WS;        // [CC][CC]
    float* dw  = ah  + NF_AH;        // [C2][CC] (16B aligned)
    float* es0 = dw  + NF_DW;        // [F1][CC][ES_S] buffer 0
    float* es1 = es0 + NF_ES1;       // buffer 1
    float* xg  = es1 + NF_ES1;       // [CC][TSUB]
    float* m0  = xg  + NF_XG;        // [C2][CC] (16B aligned)
    float* ps  = m0  + NF_M0;        // [C2][TSUB]
    float* o1s = ps  + NF_PS;        // [F1]
    float* gw  = o1s + F1N;          // [F1]
    float* s2  = gw  + F1N;          // [C2]
    float* sh2 = s2  + C2N;          // [C2]
    float* cst = sh2 + C2N;          // [C2]

    const int tid = threadIdx.x;
    const int b   = blockIdx.y;
    const int t0  = blockIdx.x * TILE;

    // ---- cooperative loads (all 1024 threads) ----
    for (int i = tid; i < NF_XS; i += 1024) {
        int c = i / XS_W, j = i % XS_W;
        int tg = t0 - 31 + j;
        xs[i] = (tg >= 0 && tg < TTOT) ? x[(b * CC + c) * TTOT + tg] : 0.f;
    }
    for (int i = tid; i < NF_WS; i += 1024) {
        int f = i / KK;
        float s1 = g1[f] * rsqrtf(v1[f] + EPSF);
        ws[i] = w1[i] * s1;
    }
    for (int i = tid; i < NF_AH; i += 1024) ah[i] = ahat_g[i];
    for (int i = tid; i < NF_DW; i += 1024) dw[i] = dww_g[i];
    if (tid < F1N) {
        float s1 = g1[tid] * rsqrtf(v1[tid] + EPSF);
        o1s[tid] = b1c[tid] * s1 + bb1[tid] - m1[tid] * s1;
        gw[tid]  = gcw[tid];
    }
    if (tid < C2N) {
        float s = g2[tid] * rsqrtf(v2[tid] + EPSF);
        s2[tid]  = s;
        sh2[tid] = bb2[tid] - m2[tid] * s;
    }
    __syncthreads();
    if (tid < C2N) {
        float wsum = 0.f;
        for (int c = 0; c < CC; ++c) wsum += dw[tid * CC + c];
        cst[tid] = gcb[tid >> 1] * wsum + dwb[tid];
    }
    // M0 = (gw/F1) * dw @ ahat
    for (int it = tid; it < C2N * CC; it += 1024) {
        int c2 = it >> 6, j = it & 63;
        const float* dr = dw + c2 * CC;
        float s = 0.f;
        #pragma unroll 8
        for (int cc = 0; cc < CC; ++cc)
            s = fmaf(dr[cc], ah[cc * CC + j], s);
        m0[it] = s * gw[c2 >> 1] * (1.f / F1N);
    }
    __syncthreads();   // last full-block barrier before role split

    if (tid < 512) {
        // ================= CONV PRODUCER (warps 0-15) =================
        const int fpair = tid >> 6;       // 0..7
        const int c     = tid & 63;
        const float* xrow = xs + c * XS_W;

        for (int chk = 0; chk < NCHUNK; ++chk) {
            const int p  = chk & 1;
            const int ct = chk * TSUB;
            float* esb = p ? es1 : es0;
            if (chk >= 2) BAR_SYNC(4 + p, 1024);   // wait es[p] consumed

            #pragma unroll 1
            for (int sub = 0; sub < 2; ++sub) {
                const int f = fpair + 8 * sub;
                const float* wr = ws + f * KK;
                const float o1 = o1s[f];
                float acc[TSUB], win[TSUB];
                #pragma unroll
                for (int i = 0; i < TSUB; ++i) {
                    acc[i] = 0.f;
                    win[i] = xrow[ct + i];
                }
                int k = 0;
                #pragma unroll 1
                for (int m = 0; m < 4; ++m) {
                    #pragma unroll
                    for (int kk = 0; kk < 16; ++kk) {
                        float w = wr[k + kk];
                        #pragma unroll
                        for (int i = 0; i < TSUB; ++i)
                            acc[i] = fmaf(w, win[(kk + i) & 15], acc[i]);
                        win[kk] = xrow[ct + k + kk + TSUB];
                    }
                    k += 16;
                }
                float* erow = esb + (f * CC + c) * ES_S;
                #pragma unroll
                for (int i = 0; i < TSUB; ++i)
                    erow[i] = eluf(acc[i] + o1);
            }
            __threadfence_block();
            BAR_ARRIVE(2 + p, 1024);               // signal es[p] full
        }
    } else {
        // ================= PHASE CONSUMER (warps 16-31) =================
        const int tl  = tid - 512;        // 0..511
        const int c2  = tl >> 4;
        const int tt  = tl & 15;
        const int ff  = c2 >> 1;
        float stat_s = 0.f, stat_m = -INFINITY;

        for (int chk = 0; chk < NCHUNK; ++chk) {
            const int p = chk & 1;
            const float* esb = p ? es1 : es0;
            BAR_SYNC(2 + p, 1024);                 // wait es[p] full

            // phase 2: xg (2 items) + ps (1 item)
            #pragma unroll
            for (int r = 0; r < 2; ++r) {
                int item = tl + r * 512;
                int cc = item >> 4, tti = item & 15;
                const float* er = esb + cc * ES_S + tti;
                float s = 0.f;
                #pragma unroll
                for (int f2 = 0; f2 < F1N; ++f2)
                    s += er[f2 * CC * ES_S];
                xg[item] = s;                      // raw sum (M0 holds /F1)
            }
            {
                const float4* dr4 = (const float4*)(dw + c2 * CC);
                const float* er = esb + ff * CC * ES_S + tt;
                float s = 0.f;
                #pragma unroll
                for (int q = 0; q < 16; ++q) {
                    float4 d = dr4[q];
                    int cc = q * 4;
                    s = fmaf(d.x, er[(cc + 0) * ES_S], s);
                    s = fmaf(d.y, er[(cc + 1) * ES_S], s);
                    s = fmaf(d.z, er[(cc + 2) * ES_S], s);
                    s = fmaf(d.w, er[(cc + 3) * ES_S], s);
                }
                ps[tl] = s;
            }
            BAR_SYNC(6, 512);                      // es reads + xg/ps done
            BAR_ARRIVE(4 + p, 1024);               // conv may overwrite es[p]

            // phase 3: combine + BN2 -> g_h2 + stats
            {
                const float4* mr4 = (const float4*)(m0 + c2 * CC);
                const float* xr = xg + tt;
                float s = ps[tl];
                #pragma unroll
                for (int q = 0; q < 16; ++q) {
                    float4 m = mr4[q];
                    int j = q * 4;
                    s = fmaf(m.x, xr[(j + 0) * TSUB], s);
                    s = fmaf(m.y, xr[(j + 1) * TSUB], s);
                    s = fmaf(m.z, xr[(j + 2) * TSUB], s);
                    s = fmaf(m.w, xr[(j + 3) * TSUB], s);
                }
                float outv = (s + cst[c2]) * s2[c2] + sh2[c2];
                int t = t0 + chk * TSUB + tt;
                bool valid = (t < TTOT);
                if (valid) g_h2[(b * C2N + c2) * TTOT + t] = outv;
                float sv = valid ? outv : 0.f;
                float mv = valid ? outv : -INFINITY;
                #pragma unroll
                for (int o = 8; o > 0; o >>= 1) {
                    sv += __shfl_down_sync(0xffffffffu, sv, o, 16);
                    mv  = fmaxf(mv, __shfl_down_sync(0xffffffffu, mv, o, 16));
                }
                if (tt == 0) { stat_s += sv; stat_m = fmaxf(stat_m, mv); }
            }
            BAR_SYNC(6, 512);                      // xg/ps reads done
        }

        if (tt == 0) {
            g_psum[(b * C2N + c2) * NTILE + blockIdx.x] = stat_s;
            g_pmax[(b * C2N + c2) * NTILE + blockIdx.x] = stat_m;
        }
    }
}

// ============================================================
// Kernel 2b: channel attn + spatial attn + ELU + pool16 -> g_q
// ============================================================
#define H2S_S 131
__global__ void __launch_bounds__(256, 4)
k2b_attpool(const float* __restrict__ caw1, const float* __restrict__ cab1,
            const float* __restrict__ caw2, const float* __restrict__ cab2,
            const float* __restrict__ saw,
            const float* __restrict__ sag, const float* __restrict__ sab,
            const float* __restrict__ sam, const float* __restrict__ sav)
{
    __shared__ float att[C2N];
    __shared__ float h2s[C2N * H2S_S];
    __shared__ float mms[K2B_T + 2], mxs[K2B_T + 2], sgs[K2B_T];
    __shared__ float sstat[C2N];

    const int tile = blockIdx.x, b = blockIdx.y;
    const int tid  = threadIdx.x;
    const int t0   = tile * K2B_T;
    const int tw   = (tile == NTILE2 - 1) ? (NPOOL * PWN - t0) : K2B_T;
    const int nw   = tw / PWN;

    if (tid < C2N) {
        float s = 0.f, m = -INFINITY;
        const float* pss = g_psum + (b * C2N + tid) * NTILE;
        const float* pm = g_pmax + (b * C2N + tid) * NTILE;
        #pragma unroll
        for (int tl = 0; tl < NTILE; ++tl) {
            s += pss[tl]; m = fmaxf(m, pm[tl]);
        }
        sstat[tid] = s * (1.f / TTOT) + m;
    }
    __syncthreads();
    if (tid < C2N) {
        float r0 = cab1[0], r1 = cab1[1];
        for (int j = 0; j < C2N; ++j) {
            r0 += caw1[j] * sstat[j];
            r1 += caw1[C2N + j] * sstat[j];
        }
        r0 = fmaxf(r0, 0.f); r1 = fmaxf(r1, 0.f);
        att[tid] = sigmf(cab2[tid] + caw2[tid * 2] * r0 + caw2[tid * 2 + 1] * r1);
    }
    __syncthreads();

    const float* h2 = g_h2 + b * C2N * TTOT;
    for (int idx = tid; idx < C2N * (tw + 2); idx += 256) {
        int c2 = idx / (tw + 2), j = idx % (tw + 2);
        int t = t0 - 1 + j;
        float v = (t >= 0 && t < TTOT) ? h2[c2 * TTOT + t] * att[c2] : 0.f;
        h2s[c2 * H2S_S + j] = v;
    }
    __syncthreads();

    for (int j = tid; j < tw + 2; j += 256) {
        float s = 0.f, mx = -INFINITY;
        #pragma unroll 8
        for (int c2 = 0; c2 < C2N; ++c2) {
            float v = h2s[c2 * H2S_S + j];
            s += v; mx = fmaxf(mx, v);
        }
        mms[j] = s * (1.f / C2N);
        mxs[j] = mx;
    }
    __syncthreads();

    {
        float ssa = sag[0] * rsqrtf(sav[0] + EPSF);
        float sha = sab[0] - sam[0] * ssa;
        for (int j = tid; j < tw; j += 256) {
            int t = t0 + j;
            float acc = 0.f;
            #pragma unroll
            for (int kw = 0; kw < 3; ++kw) {
                int tt = t - 1 + kw;
                if (tt >= 0 && tt < TTOT)
                    acc += saw[3 + kw] * mms[j + kw] + saw[12 + kw] * mxs[j + kw];
            }
            sgs[j] = sigmf(acc * ssa + sha);
        }
    }
    __syncthreads();

    {
        int c2 = tid & 31, w = tid >> 5;
        if (w < nw) {
            float acc = 0.f;
            #pragma unroll
            for (int j = 0; j < PWN; ++j) {
                int tl = w * PWN + j;
                acc += eluf(h2s[c2 * H2S_S + tl + 1] * sgs[tl]);
            }
            g_q[(b * C2N + c2) * NPOOL + tile * K2B_W + w] = acc * (1.f / PWN);
        }
    }
}

// ============================================================
// Kernel 2c: depthwise sep conv + BN3 + ELU + pool16 -> out
// ============================================================
__global__ void __launch_bounds__(256, 4)
k2c_tail(const float* __restrict__ sepw, const float* __restrict__ sepb,
         const float* __restrict__ g3, const float* __restrict__ bb3,
         const float* __restrict__ m3, const float* __restrict__ v3,
         float* __restrict__ out)
{
    __shared__ float qs[C2N * NPOOL];
    __shared__ float sw[C2N * PWN];
    const int b = blockIdx.x, tid = threadIdx.x;
    for (int i = tid; i < C2N * NPOOL; i += 256)
        qs[i] = g_q[b * C2N * NPOOL + i];
    for (int i = tid; i < C2N * PWN; i += 256)
        sw[i] = sepw[i];
    __syncthreads();

    const int j  = tid & 15;
    const int e0 = tid >> 4;
    for (int r = 0; r < 6; ++r) {
        int e  = e0 + r * 16;          // 0..95 = c2*3 + to
        int c2 = e / 3, to = e % 3;
        int t  = to * PWN + j;
        float y = sepb[c2];
        #pragma unroll
        for (int u = 0; u < PWN; ++u) {
            int tq = t - 7 + u;
            if (tq >= 0 && tq < NPOOL) y = fmaf(sw[c2 * PWN + u], qs[c2 * NPOOL + tq], y);
        }
        float s3  = g3[c2] * rsqrtf(v3[c2] + EPSF);
        float sh3 = bb3[c2] - m3[c2] * s3;
        float v = eluf(y * s3 + sh3);
        #pragma unroll
        for (int o = 8; o > 0; o >>= 1)
            v += __shfl_down_sync(0xffffffffu, v, o, 16);
        if (j == 0) out[b * (C2N * 3) + e] = v * (1.f / PWN);
    }
}

// ============================================================
extern "C" void kernel_launch(void* const* d_in, const int* in_sizes, int n_in,
                              void* d_out, int out_size)
{
    const float* x     = (const float*)d_in[0];
    const float* ahat  = (const float*)d_in[1];
    const float* w1    = (const float*)d_in[2];
    const float* b1c   = (const float*)d_in[3];
    const float* g1    = (const float*)d_in[4];
    const float* bb1   = (const float*)d_in[5];
    const float* m1    = (const float*)d_in[6];
    const float* v1    = (const float*)d_in[7];
    const float* gcw   = (const float*)d_in[8];
    const float* gcb   = (const float*)d_in[9];
    const float* dww   = (const float*)d_in[10];
    const float* dwb   = (const float*)d_in[11];
    const float* g2    = (const float*)d_in[12];
    const float* bb2   = (const float*)d_in[13];
    const float* m2    = (const float*)d_in[14];
    const float* v2    = (const float*)d_in[15];
    const float* caw1  = (const float*)d_in[16];
    const float* cab1  = (const float*)d_in[17];
    const float* caw2  = (const float*)d_in[18];
    const float* cab2  = (const float*)d_in[19];
    const float* saw   = (const float*)d_in[20];
    const float* sag   = (const float*)d_in[21];
    const float* sab   = (const float*)d_in[22];
    const float* sam   = (const float*)d_in[23];
    const float* sav   = (const float*)d_in[24];
    const float* sepw  = (const float*)d_in[25];
    const float* sepb  = (const float*)d_in[26];
    const float* g3    = (const float*)d_in[27];
    const float* bb3   = (const float*)d_in[28];
    const float* m3    = (const float*)d_in[29];
    const float* v3    = (const float*)d_in[30];

    cudaFuncSetAttribute(k1_front, cudaFuncAttributeMaxDynamicSharedMemorySize,
                         SMEM_BYTES);

    dim3 grid1(NTILE, BB);
    k1_front<<<grid1, 1024, SMEM_BYTES>>>(x, ahat, w1, b1c, g1, bb1, m1, v1,
                                          gcw, gcb, dww, dwb, g2, bb2, m2, v2);

    dim3 grid2b(NTILE2, BB);
    k2b_attpool<<<grid2b, 256>>>(caw1, cab1, caw2, cab2, saw, sag, sab, sam, sav);

    k2c_tail<<<BB, 256>>>(sepw, sepb, g3, bb3, m3, v3, (float*)d_out);
}

// round 13
// speedup vs baseline: 1.2514x; 1.1458x over previous
#include <cuda_runtime.h>
#include <math.h>

// ---------------- problem constants ----------------
#define BB     16
#define F1N    16
#define CC     64
#define TTOT   1000
#define KK     64
#define C2N    32
#define PWN    16
#define EPSF   1e-5f

// ---------------- kernel-1 tiling ----------------
#define TILE   112         // time points per block
#define NTILE  9           // 9*112 = 1008 >= 1000 (last tile partial)
#define TSUB   16          // chunk of t per phase round
#define NCHUNK 7           // 7*16 = 112
#define XS_W   177         // TILE + 63 halo + 2 (odd -> conflict-free)
#define ES_S   17          // es row stride (odd -> conflict-free)

// smem float counts
#define NF_XS   (CC*XS_W)       // 11328
#define NF_WS   (F1N*KK)        // 1024
#define NF_AH   (CC*CC)         // 4096 (reused as xg/ps double buffers)
#define NF_DW   (C2N*CC)        // 2048
#define NF_ES1  (F1N*CC*ES_S)   // 17408 (one buffer)
#define NF_M0   (C2N*CC)        // 2048
#define NF_SMALL 144
#define SMEM_FLOATS (NF_XS+NF_WS+NF_AH+NF_DW+2*NF_ES1+NF_M0+NF_SMALL)
#define SMEM_BYTES  (SMEM_FLOATS*4)   // ~222 KB <= 232448 cap

// K2 tiling
#define K2B_W    8
#define K2B_T    (K2B_W*PWN)  // 128
#define NTILE2   8
#define NPOOL    62

__device__ float g_h2[BB * C2N * TTOT];
__device__ float g_psum[BB * C2N * NTILE];
__device__ float g_pmax[BB * C2N * NTILE];
__device__ float g_q[BB * C2N * NPOOL];

__device__ __forceinline__ float eluf(float v) {
    // fast ELU: MUFU-based exp. |abs err| ~2e-7 on e^v; fine vs 1e-3 gate.
    return v > 0.f ? v : (__expf(v) - 1.f);
}
__device__ __forceinline__ float sigmf(float z) { return 1.f / (1.f + __expf(-z)); }

#define BAR_SYNC(id, cnt)   asm volatile("bar.sync %0, %1;"   :: "r"(id), "r"(cnt) : "memory")
#define BAR_ARRIVE(id, cnt) asm volatile("bar.arrive %0, %1;" :: "r"(id), "r"(cnt) : "memory")

// ============================================================
// Kernel 1: warp-specialized producer/consumer.
//  warps 0-15 : temporal conv (2 filters / shared window) -> es[p]
//  warps 16-31: GCN/expansion/BN2 -> g_h2 + stats
// grid (NTILE, BB) = 144 blocks, 1024 threads
// ============================================================
__global__ void __launch_bounds__(1024, 1)
k1_front(const float* __restrict__ x,
         const float* __restrict__ ahat_g,
         const float* __restrict__ w1,  const float* __restrict__ b1c,
         const float* __restrict__ g1,  const float* __restrict__ bb1,
         const float* __restrict__ m1,  const float* __restrict__ v1,
         const float* __restrict__ gcw, const float* __restrict__ gcb,
         const float* __restrict__ dww_g, const float* __restrict__ dwb,
         const float* __restrict__ g2,  const float* __restrict__ bb2,
         const float* __restrict__ m2,  const float* __restrict__ v2)
{
    extern __shared__ float sm[];
    float* xs  = sm;                 // [CC][XS_W]
    float* ws  = xs  + NF_XS;        // [F1][KK] (BN1-scaled weights)
    float* ah  = ws  + NF_WS;        // [CC][CC]; later xg/ps buffers
    float* dw  = ah  + NF_AH;        // [C2][CC] (16B aligned)
    float* es0 = dw  + NF_DW;        // [F1][CC][ES_S] buffer 0
    float* es1 = es0 + NF_ES1;       // buffer 1
    float* m0  = es1 + NF_ES1;       // [C2][CC] (16B aligned)
    float* o1s = m0  + NF_M0;        // [F1]
    float* gw  = o1s + F1N;          // [F1]
    float* s2  = gw  + F1N;          // [C2]
    float* sh2 = s2  + C2N;          // [C2]
    float* cst = sh2 + C2N;          // [C2]

    const int tid = threadIdx.x;
    const int b   = blockIdx.y;
    const int t0  = blockIdx.x * TILE;

    // ---- cooperative loads (all 1024 threads) ----
    for (int i = tid; i < NF_XS; i += 1024) {
        int c = i / XS_W, j = i % XS_W;
        int tg = t0 - 31 + j;
        xs[i] = (tg >= 0 && tg < TTOT) ? x[(b * CC + c) * TTOT + tg] : 0.f;
    }
    for (int i = tid; i < NF_WS; i += 1024) {
        int f = i / KK;
        float s1 = g1[f] * rsqrtf(v1[f] + EPSF);
        ws[i] = w1[i] * s1;
    }
    for (int i = tid; i < NF_AH; i += 1024) ah[i] = ahat_g[i];
    for (int i = tid; i < NF_DW; i += 1024) dw[i] = dww_g[i];
    if (tid < F1N) {
        float s1 = g1[tid] * rsqrtf(v1[tid] + EPSF);
        o1s[tid] = b1c[tid] * s1 + bb1[tid] - m1[tid] * s1;
        gw[tid]  = gcw[tid];
    }
    if (tid < C2N) {
        float s = g2[tid] * rsqrtf(v2[tid] + EPSF);
        s2[tid]  = s;
        sh2[tid] = bb2[tid] - m2[tid] * s;
    }
    __syncthreads();
    if (tid < C2N) {
        float wsum = 0.f;
        for (int c = 0; c < CC; ++c) wsum += dw[tid * CC + c];
        cst[tid] = gcb[tid >> 1] * wsum + dwb[tid];
    }
    // M0 = (gw/F1) * dw @ ahat
    for (int it = tid; it < C2N * CC; it += 1024) {
        int c2 = it >> 6, j = it & 63;
        const float* dr = dw + c2 * CC;
        float s = 0.f;
        #pragma unroll 8
        for (int cc = 0; cc < CC; ++cc)
            s = fmaf(dr[cc], ah[cc * CC + j], s);
        m0[it] = s * gw[c2 >> 1] * (1.f / F1N);
    }
    __syncthreads();   // ah dead after this point -> reused as xg/ps buffers

    if (tid < 512) {
        // ================= CONV PRODUCER (warps 0-15) =================
        // thread -> (fpair 0..7, c 0..63); computes filters fpair and fpair+8
        const int fpair = tid >> 6;
        const int c     = tid & 63;
        const float* xrow = xs + c * XS_W;
        const float* wr0 = ws + fpair * KK;
        const float* wr1 = ws + (fpair + 8) * KK;
        const float o0 = o1s[fpair], o1v = o1s[fpair + 8];

        for (int chk = 0; chk < NCHUNK; ++chk) {
            const int p  = chk & 1;
            const int ct = chk * TSUB;
            float* esb = p ? es1 : es0;
            if (chk >= 2) BAR_SYNC(4 + p, 1024);   // wait es[p] consumed

            float acc0[TSUB], acc1[TSUB], win[TSUB];
            #pragma unroll
            for (int i = 0; i < TSUB; ++i) {
                acc0[i] = acc1[i] = 0.f;
                win[i] = xrow[ct + i];
            }
            int k = 0;
            #pragma unroll 1
            for (int m = 0; m < 4; ++m) {
                #pragma unroll
                for (int kk = 0; kk < 16; ++kk) {
                    float w0 = wr0[k + kk], w1v = wr1[k + kk];
                    #pragma unroll
                    for (int i = 0; i < TSUB; ++i) {
                        float xv = win[(kk + i) & 15];
                        acc0[i] = fmaf(w0, xv, acc0[i]);
                        acc1[i] = fmaf(w1v, xv, acc1[i]);
                    }
                    win[kk] = xrow[ct + k + kk + TSUB];
                }
                k += 16;
            }
            float* e0 = esb + (fpair * CC + c) * ES_S;
            float* e1 = esb + ((fpair + 8) * CC + c) * ES_S;
            #pragma unroll
            for (int i = 0; i < TSUB; ++i) {
                e0[i] = eluf(acc0[i] + o0);
                e1[i] = eluf(acc1[i] + o1v);
            }
            __threadfence_block();
            BAR_ARRIVE(2 + p, 1024);               // signal es[p] full
        }
    } else {
        // ================= PHASE CONSUMER (warps 16-31) =================
        const int tl  = tid - 512;        // 0..511
        const int c2  = tl >> 4;
        const int tt  = tl & 15;
        const int ff  = c2 >> 1;
        float stat_s = 0.f, stat_m = -INFINITY;

        for (int chk = 0; chk < NCHUNK; ++chk) {
            const int p = chk & 1;
            const float* esb = p ? es1 : es0;
            float* xgb = ah + p * 2048;            // [CC*TSUB] = 1024
            float* psb = xgb + 1024;               // [C2*TSUB] = 512
            BAR_SYNC(2 + p, 1024);                 // wait es[p] full

            // phase 2: xg (2 items) + ps (1 item)
            #pragma unroll
            for (int r = 0; r < 2; ++r) {
                int item = tl + r * 512;
                int cc = item >> 4, tti = item & 15;
                const float* er = esb + cc * ES_S + tti;
                float s = 0.f;
                #pragma unroll
                for (int f2 = 0; f2 < F1N; ++f2)
                    s += er[f2 * CC * ES_S];
                xgb[item] = s;                     // raw sum (M0 holds /F1)
            }
            {
                const float4* dr4 = (const float4*)(dw + c2 * CC);
                const float* er = esb + ff * CC * ES_S + tt;
                float s = 0.f;
                #pragma unroll
                for (int q = 0; q < 16; ++q) {
                    float4 d = dr4[q];
                    int cc = q * 4;
                    s = fmaf(d.x, er[(cc + 0) * ES_S], s);
                    s = fmaf(d.y, er[(cc + 1) * ES_S], s);
                    s = fmaf(d.z, er[(cc + 2) * ES_S], s);
                    s = fmaf(d.w, er[(cc + 3) * ES_S], s);
                }
                psb[tl] = s;
            }
            BAR_SYNC(6, 512);                      // es reads + xg writes done
            BAR_ARRIVE(4 + p, 1024);               // conv may overwrite es[p]

            // phase 3: combine + BN2 -> g_h2 + stats
            {
                const float4* mr4 = (const float4*)(m0 + c2 * CC);
                const float* xr = xgb + tt;
                float s = psb[tl];
                #pragma unroll
                for (int q = 0; q < 16; ++q) {
                    float4 m = mr4[q];
                    int j = q * 4;
                    s = fmaf(m.x, xr[(j + 0) * TSUB], s);
                    s = fmaf(m.y, xr[(j + 1) * TSUB], s);
                    s = fmaf(m.z, xr[(j + 2) * TSUB], s);
                    s = fmaf(m.w, xr[(j + 3) * TSUB], s);
                }
                float outv = (s + cst[c2]) * s2[c2] + sh2[c2];
                int t = t0 + chk * TSUB + tt;
                bool valid = (t < TTOT);
                if (valid) g_h2[(b * C2N + c2) * TTOT + t] = outv;
                float sv = valid ? outv : 0.f;
                float mv = valid ? outv : -INFINITY;
                #pragma unroll
                for (int o = 8; o > 0; o >>= 1) {
                    sv += __shfl_down_sync(0xffffffffu, sv, o, 16);
                    mv  = fmaxf(mv, __shfl_down_sync(0xffffffffu, mv, o, 16));
                }
                if (tt == 0) { stat_s += sv; stat_m = fmaxf(stat_m, mv); }
            }
            // no trailing barrier: next chunk writes the other parity buffer
        }

        if (tt == 0) {
            g_psum[(b * C2N + c2) * NTILE + blockIdx.x] = stat_s;
            g_pmax[(b * C2N + c2) * NTILE + blockIdx.x] = stat_m;
        }
    }
}

// ============================================================
// Kernel 2b: channel attn + spatial attn + ELU + pool16 -> g_q
// ============================================================
#define H2S_S 131
__global__ void __launch_bounds__(256, 4)
k2b_attpool(const float* __restrict__ caw1, const float* __restrict__ cab1,
            const float* __restrict__ caw2, const float* __restrict__ cab2,
            const float* __restrict__ saw,
            const float* __restrict__ sag, const float* __restrict__ sab,
            const float* __restrict__ sam, const float* __restrict__ sav)
{
    __shared__ float att[C2N];
    __shared__ float h2s[C2N * H2S_S];
    __shared__ float mms[K2B_T + 2], mxs[K2B_T + 2], sgs[K2B_T];
    __shared__ float sstat[C2N];

    const int tile = blockIdx.x, b = blockIdx.y;
    const int tid  = threadIdx.x;
    const int t0   = tile * K2B_T;
    const int tw   = (tile == NTILE2 - 1) ? (NPOOL * PWN - t0) : K2B_T;
    const int nw   = tw / PWN;

    if (tid < C2N) {
        float s = 0.f, m = -INFINITY;
        const float* pss = g_psum + (b * C2N + tid) * NTILE;
        const float* pm = g_pmax + (b * C2N + tid) * NTILE;
        #pragma unroll
        for (int tl = 0; tl < NTILE; ++tl) {
            s += pss[tl]; m = fmaxf(m, pm[tl]);
        }
        sstat[tid] = s * (1.f / TTOT) + m;
    }
    __syncthreads();
    if (tid < C2N) {
        float r0 = cab1[0], r1 = cab1[1];
        for (int j = 0; j < C2N; ++j) {
            r0 += caw1[j] * sstat[j];
            r1 += caw1[C2N + j] * sstat[j];
        }
        r0 = fmaxf(r0, 0.f); r1 = fmaxf(r1, 0.f);
        float z = cab2[tid] + caw2[tid * 2] * r0 + caw2[tid * 2 + 1] * r1;
        att[tid] = 1.f / (1.f + expf(-z));
    }
    __syncthreads();

    const float* h2 = g_h2 + b * C2N * TTOT;
    for (int idx = tid; idx < C2N * (tw + 2); idx += 256) {
        int c2 = idx / (tw + 2), j = idx % (tw + 2);
        int t = t0 - 1 + j;
        float v = (t >= 0 && t < TTOT) ? h2[c2 * TTOT + t] * att[c2] : 0.f;
        h2s[c2 * H2S_S + j] = v;
    }
    __syncthreads();

    for (int j = tid; j < tw + 2; j += 256) {
        float s = 0.f, mx = -INFINITY;
        #pragma unroll 8
        for (int c2 = 0; c2 < C2N; ++c2) {
            float v = h2s[c2 * H2S_S + j];
            s += v; mx = fmaxf(mx, v);
        }
        mms[j] = s * (1.f / C2N);
        mxs[j] = mx;
    }
    __syncthreads();

    {
        float ssa = sag[0] * rsqrtf(sav[0] + EPSF);
        float sha = sab[0] - sam[0] * ssa;
        for (int j = tid; j < tw; j += 256) {
            int t = t0 + j;
            float acc = 0.f;
            #pragma unroll
            for (int kw = 0; kw < 3; ++kw) {
                int tt = t - 1 + kw;
                if (tt >= 0 && tt < TTOT)
                    acc += saw[3 + kw] * mms[j + kw] + saw[12 + kw] * mxs[j + kw];
            }
            float z = acc * ssa + sha;
            sgs[j] = 1.f / (1.f + expf(-z));
        }
    }
    __syncthreads();

    {
        int c2 = tid & 31, w = tid >> 5;
        if (w < nw) {
            float acc = 0.f;
            #pragma unroll
            for (int j = 0; j < PWN; ++j) {
                int tl = w * PWN + j;
                float v = h2s[c2 * H2S_S + tl + 1] * sgs[tl];
                acc += (v > 0.f ? v : expm1f(v));
            }
            g_q[(b * C2N + c2) * NPOOL + tile * K2B_W + w] = acc * (1.f / PWN);
        }
    }
}

// ============================================================
// Kernel 2c: depthwise sep conv + BN3 + ELU + pool16 -> out
// ============================================================
__global__ void __launch_bounds__(256, 4)
k2c_tail(const float* __restrict__ sepw, const float* __restrict__ sepb,
         const float* __restrict__ g3, const float* __restrict__ bb3,
         const float* __restrict__ m3, const float* __restrict__ v3,
         float* __restrict__ out)
{
    __shared__ float qs[C2N * NPOOL];
    __shared__ float sw[C2N * PWN];
    const int b = blockIdx.x, tid = threadIdx.x;
    for (int i = tid; i < C2N * NPOOL; i += 256)
        qs[i] = g_q[b * C2N * NPOOL + i];
    for (int i = tid; i < C2N * PWN; i += 256)
        sw[i] = sepw[i];
    __syncthreads();

    const int j  = tid & 15;
    const int e0 = tid >> 4;
    for (int r = 0; r < 6; ++r) {
        int e  = e0 + r * 16;          // 0..95 = c2*3 + to
        int c2 = e / 3, to = e % 3;
        int t  = to * PWN + j;
        float y = sepb[c2];
        #pragma unroll
        for (int u = 0; u < PWN; ++u) {
            int tq = t - 7 + u;
            if (tq >= 0 && tq < NPOOL) y = fmaf(sw[c2 * PWN + u], qs[c2 * NPOOL + tq], y);
        }
        float s3  = g3[c2] * rsqrtf(v3[c2] + EPSF);
        float sh3 = bb3[c2] - m3[c2] * s3;
        float yb = y * s3 + sh3;
        float v = yb > 0.f ? yb : expm1f(yb);
        #pragma unroll
        for (int o = 8; o > 0; o >>= 1)
            v += __shfl_down_sync(0xffffffffu, v, o, 16);
        if (j == 0) out[b * (C2N * 3) + e] = v * (1.f / PWN);
    }
}

// ============================================================
extern "C" void kernel_launch(void* const* d_in, const int* in_sizes, int n_in,
                              void* d_out, int out_size)
{
    const float* x     = (const float*)d_in[0];
    const float* ahat  = (const float*)d_in[1];
    const float* w1    = (const float*)d_in[2];
    const float* b1c   = (const float*)d_in[3];
    const float* g1    = (const float*)d_in[4];
    const float* bb1   = (const float*)d_in[5];
    const float* m1    = (const float*)d_in[6];
    const float* v1    = (const float*)d_in[7];
    const float* gcw   = (const float*)d_in[8];
    const float* gcb   = (const float*)d_in[9];
    const float* dww   = (const float*)d_in[10];
    const float* dwb   = (const float*)d_in[11];
    const float* g2    = (const float*)d_in[12];
    const float* bb2   = (const float*)d_in[13];
    const float* m2    = (const float*)d_in[14];
    const float* v2    = (const float*)d_in[15];
    const float* caw1  = (const float*)d_in[16];
    const float* cab1  = (const float*)d_in[17];
    const float* caw2  = (const float*)d_in[18];
    const float* cab2  = (const float*)d_in[19];
    const float* saw   = (const float*)d_in[20];
    const float* sag   = (const float*)d_in[21];
    const float* sab   = (const float*)d_in[22];
    const float* sam   = (const float*)d_in[23];
    const float* sav   = (const float*)d_in[24];
    const float* sepw  = (const float*)d_in[25];
    const float* sepb  = (const float*)d_in[26];
    const float* g3    = (const float*)d_in[27];
    const float* bb3   = (const float*)d_in[28];
    const float* m3    = (const float*)d_in[29];
    const float* v3    = (const float*)d_in[30];

    cudaFuncSetAttribute(k1_front, cudaFuncAttributeMaxDynamicSharedMemorySize,
                         SMEM_BYTES);

    dim3 grid1(NTILE, BB);
    k1_front<<<grid1, 1024, SMEM_BYTES>>>(x, ahat, w1, b1c, g1, bb1, m1, v1,
                                          gcw, gcb, dww, dwb, g2, bb2, m2, v2);

    dim3 grid2b(NTILE2, BB);
    k2b_attpool<<<grid2b, 256>>>(caw1, cab1, caw2, cab2, saw, sag, sab, sam, sav);

    k2c_tail<<<BB, 256>>>(sepw, sepb, g3, bb3, m3, v3, (float*)d_out);
}

// round 15
// speedup vs baseline: 1.3139x; 1.0500x over previous
#include <cuda_runtime.h>
#include <math.h>

// ---------------- problem constants ----------------
#define BB     16
#define F1N    16
#define CC     64
#define TTOT   1000
#define KK     64
#define C2N    32
#define PWN    16
#define EPSF   1e-5f

// ---------------- kernel-1 tiling ----------------
#define TILE   112         // time points per block
#define NTILE  9           // 9*112 = 1008 >= 1000 (last tile partial)
#define TSUB   16          // chunk of t per phase round
#define NCHUNK 7           // 7*16 = 112
#define XS_W   177         // TILE + 63 halo + 2 (odd -> conflict-free)
#define ES_S   17          // es row stride (odd -> conflict-free)

// smem float counts
#define NF_XS   (CC*XS_W)       // 11328
#define NF_WS   (F1N*KK)        // 1024
#define NF_AH   (CC*CC)         // 4096 (reused as xg/ps double buffers)
#define NF_DW   (C2N*CC)        // 2048
#define NF_ES1  (F1N*CC*ES_S)   // 17408 (one buffer)
#define NF_M0   (C2N*CC)        // 2048
#define NF_SMALL 144
#define SMEM_FLOATS (NF_XS+NF_WS+NF_AH+NF_DW+2*NF_ES1+NF_M0+NF_SMALL)
#define SMEM_BYTES  (SMEM_FLOATS*4)   // ~222 KB <= 232448 cap

// K2 tiling
#define K2B_W    8
#define K2B_T    (K2B_W*PWN)  // 128
#define NTILE2   8
#define NPOOL    62

__device__ float g_h2[BB * C2N * TTOT];
__device__ float g_psum[BB * C2N * NTILE];
__device__ float g_pmax[BB * C2N * NTILE];
__device__ float g_q[BB * C2N * NPOOL];
__device__ int   g_cnt[BB];          // zero-init; reset by last block each run

__device__ __forceinline__ float eluf(float v) {
    return v > 0.f ? v : (__expf(v) - 1.f);   // MUFU exp; err ~2e-7
}

#define BAR_SYNC(id, cnt)   asm volatile("bar.sync %0, %1;"   :: "r"(id), "r"(cnt) : "memory")
#define BAR_ARRIVE(id, cnt) asm volatile("bar.arrive %0, %1;" :: "r"(id), "r"(cnt) : "memory")

// ============================================================
// Kernel 1: warp-specialized producer/consumer with split prologue.
//  warps 0-15 : stage xs/ws -> temporal conv (2 filters/window) -> es[p]
//  warps 16-31: stage ah/dw -> M0 -> GCN/expansion/BN2 -> g_h2 + stats
// grid (NTILE, BB) = 144 blocks, 1024 threads
// ============================================================
__global__ void __launch_bounds__(1024, 1)
k1_front(const float* __restrict__ x,
         const float* __restrict__ ahat_g,
         const float* __restrict__ w1,  const float* __restrict__ b1c,
         const float* __restrict__ g1,  const float* __restrict__ bb1,
         const float* __restrict__ m1,  const float* __restrict__ v1,
         const float* __restrict__ gcw, const float* __restrict__ gcb,
         const float* __restrict__ dww_g, const float* __restrict__ dwb,
         const float* __restrict__ g2,  const float* __restrict__ bb2,
         const float* __restrict__ m2,  const float* __restrict__ v2)
{
    extern __shared__ float sm[];
    float* xs  = sm;                 // [CC][XS_W]
    float* ws  = xs  + NF_XS;        // [F1][KK] (BN1-scaled weights)
    float* ah  = ws  + NF_WS;        // [CC][CC]; later xg/ps parity buffers
    float* dw  = ah  + NF_AH;        // [C2][CC] (16B aligned)
    float* es0 = dw  + NF_DW;        // [F1][CC][ES_S] buffer 0
    float* es1 = es0 + NF_ES1;       // buffer 1
    float* m0  = es1 + NF_ES1;       // [C2][CC] (16B aligned)
    float* o1s = m0  + NF_M0;        // [F1]
    float* s2  = o1s + F1N + F1N;    // [C2] (gw slot unused)
    float* sh2 = s2  + C2N;          // [C2]
    float* cst = sh2 + C2N;          // [C2]

    const int tid = threadIdx.x;
    const int b   = blockIdx.y;
    const int t0  = blockIdx.x * TILE;

    if (tid < 512) {
        // ================= CONV PRODUCER (warps 0-15) =================
        // -- producer prologue: xs, ws, o1s only --
        for (int i = tid; i < NF_XS; i += 512) {
            int c = i / XS_W, j = i % XS_W;
            int tg = t0 - 31 + j;
            xs[i] = (tg >= 0 && tg < TTOT) ? x[(b * CC + c) * TTOT + tg] : 0.f;
        }
        for (int i = tid; i < NF_WS; i += 512) {
            int f = i / KK;
            float s1 = g1[f] * rsqrtf(v1[f] + EPSF);
            ws[i] = w1[i] * s1;
        }
        if (tid < F1N) {
            float s1 = g1[tid] * rsqrtf(v1[tid] + EPSF);
            o1s[tid] = b1c[tid] * s1 + bb1[tid] - m1[tid] * s1;
        }
        BAR_SYNC(1, 512);            // producer staging complete

        const int fpair = tid >> 6;  // 0..7; computes filters fpair, fpair+8
        const int c     = tid & 63;
        const float* xrow = xs + c * XS_W;
        const float* wr0 = ws + fpair * KK;
        const float* wr1 = ws + (fpair + 8) * KK;
        const float o0 = o1s[fpair], o1v = o1s[fpair + 8];

        for (int chk = 0; chk < NCHUNK; ++chk) {
            const int p  = chk & 1;
            const int ct = chk * TSUB;
            float* esb = p ? es1 : es0;
            if (chk >= 2) BAR_SYNC(4 + p, 1024);   // wait es[p] consumed

            float acc0[TSUB], acc1[TSUB], win[TSUB];
            #pragma unroll
            for (int i = 0; i < TSUB; ++i) {
                acc0[i] = acc1[i] = 0.f;
                win[i] = xrow[ct + i];
            }
            int k = 0;
            #pragma unroll 1
            for (int m = 0; m < 4; ++m) {
                #pragma unroll
                for (int kk = 0; kk < 16; ++kk) {
                    float w0 = wr0[k + kk], w1v = wr1[k + kk];
                    #pragma unroll
                    for (int i = 0; i < TSUB; ++i) {
                        float xv = win[(kk + i) & 15];
                        acc0[i] = fmaf(w0, xv, acc0[i]);
                        acc1[i] = fmaf(w1v, xv, acc1[i]);
                    }
                    win[kk] = xrow[ct + k + kk + TSUB];
                }
                k += 16;
            }
            float* e0 = esb + (fpair * CC + c) * ES_S;
            float* e1 = esb + ((fpair + 8) * CC + c) * ES_S;
            #pragma unroll
            for (int i = 0; i < TSUB; ++i) {
                e0[i] = eluf(acc0[i] + o0);
                e1[i] = eluf(acc1[i] + o1v);
            }
            __threadfence_block();
            BAR_ARRIVE(2 + p, 1024);               // signal es[p] full
        }
    } else {
        // ================= PHASE CONSUMER (warps 16-31) =================
        const int tl  = tid - 512;        // 0..511
        const int c2  = tl >> 4;
        const int tt  = tl & 15;
        const int ff  = c2 >> 1;

        // -- consumer prologue: ah, dw, BN2 params, cst, M0 --
        for (int i = tl; i < NF_AH; i += 512) ah[i] = ahat_g[i];
        for (int i = tl; i < NF_DW; i += 512) dw[i] = dww_g[i];
        if (tl < C2N) {
            float s = g2[tl] * rsqrtf(v2[tl] + EPSF);
            s2[tl]  = s;
            sh2[tl] = bb2[tl] - m2[tl] * s;
        }
        BAR_SYNC(7, 512);            // ah/dw loaded
        if (tl < C2N) {
            float wsum = 0.f;
            for (int c = 0; c < CC; ++c) wsum += dw[tl * CC + c];
            cst[tl] = gcb[tl >> 1] * wsum + dwb[tl];
        }
        for (int it = tl; it < C2N * CC; it += 512) {
            int cq = it >> 6, j = it & 63;
            const float* dr = dw + cq * CC;
            float s = 0.f;
            #pragma unroll 8
            for (int cc = 0; cc < CC; ++cc)
                s = fmaf(dr[cc], ah[cc * CC + j], s);
            m0[it] = s * gcw[cq >> 1] * (1.f / F1N);
        }
        BAR_SYNC(7, 512);            // M0 done; ah region now reusable

        float stat_s = 0.f, stat_m = -INFINITY;

        for (int chk = 0; chk < NCHUNK; ++chk) {
            const int p = chk & 1;
            const float* esb = p ? es1 : es0;
            float* xgb = ah + p * 2048;            // [CC*TSUB] = 1024
            float* psb = xgb + 1024;               // [C2*TSUB] = 512
            BAR_SYNC(2 + p, 1024);                 // wait es[p] full

            // phase 2: xg (2 items) + ps (1 item)
            #pragma unroll
            for (int r = 0; r < 2; ++r) {
                int item = tl + r * 512;
                int cc = item >> 4, tti = item & 15;
                const float* er = esb + cc * ES_S + tti;
                float s = 0.f;
                #pragma unroll
                for (int f2 = 0; f2 < F1N; ++f2)
                    s += er[f2 * CC * ES_S];
                xgb[item] = s;                     // raw sum (M0 holds /F1)
            }
            {
                const float4* dr4 = (const float4*)(dw + c2 * CC);
                const float* er = esb + ff * CC * ES_S + tt;
                float s = 0.f;
                #pragma unroll
                for (int q = 0; q < 16; ++q) {
                    float4 d = dr4[q];
                    int cc = q * 4;
                    s = fmaf(d.x, er[(cc + 0) * ES_S], s);
                    s = fmaf(d.y, er[(cc + 1) * ES_S], s);
                    s = fmaf(d.z, er[(cc + 2) * ES_S], s);
                    s = fmaf(d.w, er[(cc + 3) * ES_S], s);
                }
                psb[tl] = s;
            }
            BAR_SYNC(6, 512);                      // es reads + xg writes done
            BAR_ARRIVE(4 + p, 1024);               // conv may overwrite es[p]

            // phase 3: combine + BN2 -> g_h2 + stats
            {
                const float4* mr4 = (const float4*)(m0 + c2 * CC);
                const float* xr = xgb + tt;
                float s = psb[tl];
                #pragma unroll
                for (int q = 0; q < 16; ++q) {
                    float4 m = mr4[q];
                    int j = q * 4;
                    s = fmaf(m.x, xr[(j + 0) * TSUB], s);
                    s = fmaf(m.y, xr[(j + 1) * TSUB], s);
                    s = fmaf(m.z, xr[(j + 2) * TSUB], s);
                    s = fmaf(m.w, xr[(j + 3) * TSUB], s);
                }
                float outv = (s + cst[c2]) * s2[c2] + sh2[c2];
                int t = t0 + chk * TSUB + tt;
                bool valid = (t < TTOT);
                if (valid) g_h2[(b * C2N + c2) * TTOT + t] = outv;
                float sv = valid ? outv : 0.f;
                float mv = valid ? outv : -INFINITY;
                #pragma unroll
                for (int o = 8; o > 0; o >>= 1) {
                    sv += __shfl_down_sync(0xffffffffu, sv, o, 16);
                    mv  = fmaxf(mv, __shfl_down_sync(0xffffffffu, mv, o, 16));
                }
                if (tt == 0) { stat_s += sv; stat_m = fmaxf(stat_m, mv); }
            }
            // no trailing barrier: next chunk writes the other parity buffer
        }

        if (tt == 0) {
            g_psum[(b * C2N + c2) * NTILE + blockIdx.x] = stat_s;
            g_pmax[(b * C2N + c2) * NTILE + blockIdx.x] = stat_m;
        }
    }
}

// ============================================================
// Kernel 2: channel attn + spatial attn + ELU + pool16 -> g_q,
//  then the LAST block per batch runs the sep-conv tail -> out.
// grid (NTILE2, BB), 256 threads
// ============================================================
#define H2S_S 131
__global__ void __launch_bounds__(256, 4)
k2b_attpool(const float* __restrict__ caw1, const float* __restrict__ cab1,
            const float* __restrict__ caw2, const float* __restrict__ cab2,
            const float* __restrict__ saw,
            const float* __restrict__ sag, const float* __restrict__ sab,
            const float* __restrict__ sam, const float* __restrict__ sav,
            const float* __restrict__ sepw, const float* __restrict__ sepb,
            const float* __restrict__ g3, const float* __restrict__ bb3,
            const float* __restrict__ m3, const float* __restrict__ v3,
            float* __restrict__ out)
{
    __shared__ float att[C2N];
    __shared__ float h2s[C2N * H2S_S];
    __shared__ float mms[K2B_T + 2], mxs[K2B_T + 2], sgs[K2B_T];
    __shared__ float sstat[C2N];
    __shared__ int lastf;

    const int tile = blockIdx.x, b = blockIdx.y;
    const int tid  = threadIdx.x;
    const int t0   = tile * K2B_T;
    const int tw   = (tile == NTILE2 - 1) ? (NPOOL * PWN - t0) : K2B_T;
    const int nw   = tw / PWN;

    if (tid < C2N) {
        float s = 0.f, m = -INFINITY;
        const float* pss = g_psum + (b * C2N + tid) * NTILE;
        const float* pm = g_pmax + (b * C2N + tid) * NTILE;
        #pragma unroll
        for (int tl = 0; tl < NTILE; ++tl) {
            s += pss[tl]; m = fmaxf(m, pm[tl]);
        }
        sstat[tid] = s * (1.f / TTOT) + m;
    }
    __syncthreads();
    if (tid < C2N) {
        float r0 = cab1[0], r1 = cab1[1];
        for (int j = 0; j < C2N; ++j) {
            r0 += caw1[j] * sstat[j];
            r1 += caw1[C2N + j] * sstat[j];
        }
        r0 = fmaxf(r0, 0.f); r1 = fmaxf(r1, 0.f);
        float z = cab2[tid] + caw2[tid * 2] * r0 + caw2[tid * 2 + 1] * r1;
        att[tid] = 1.f / (1.f + expf(-z));
    }
    __syncthreads();

    const float* h2 = g_h2 + b * C2N * TTOT;
    for (int idx = tid; idx < C2N * (tw + 2); idx += 256) {
        int c2 = idx / (tw + 2), j = idx % (tw + 2);
        int t = t0 - 1 + j;
        float v = (t >= 0 && t < TTOT) ? h2[c2 * TTOT + t] * att[c2] : 0.f;
        h2s[c2 * H2S_S + j] = v;
    }
    __syncthreads();

    for (int j = tid; j < tw + 2; j += 256) {
        float s = 0.f, mx = -INFINITY;
        #pragma unroll 8
        for (int c2 = 0; c2 < C2N; ++c2) {
            float v = h2s[c2 * H2S_S + j];
            s += v; mx = fmaxf(mx, v);
        }
        mms[j] = s * (1.f / C2N);
        mxs[j] = mx;
    }
    __syncthreads();

    {
        float ssa = sag[0] * rsqrtf(sav[0] + EPSF);
        float sha = sab[0] - sam[0] * ssa;
        for (int j = tid; j < tw; j += 256) {
            int t = t0 + j;
            float acc = 0.f;
            #pragma unroll
            for (int kw = 0; kw < 3; ++kw) {
                int tt = t - 1 + kw;
                if (tt >= 0 && tt < TTOT)
                    acc += saw[3 + kw] * mms[j + kw] + saw[12 + kw] * mxs[j + kw];
            }
            float z = acc * ssa + sha;
            sgs[j] = 1.f / (1.f + expf(-z));
        }
    }
    __syncthreads();

    {
        int c2 = tid & 31, w = tid >> 5;
        if (w < nw) {
            float acc = 0.f;
            #pragma unroll
            for (int j = 0; j < PWN; ++j) {
                int tl = w * PWN + j;
                float v = h2s[c2 * H2S_S + tl + 1] * sgs[tl];
                acc += (v > 0.f ? v : expm1f(v));
            }
            g_q[(b * C2N + c2) * NPOOL + tile * K2B_W + w] = acc * (1.f / PWN);
        }
    }

    // ---- last-block-per-batch tail: sep conv + BN3 + ELU + pool16 ----
    __threadfence();
    __syncthreads();
    if (tid == 0) {
        int old = atomicAdd(&g_cnt[b], 1);
        lastf = (old == NTILE2 - 1) ? 1 : 0;
    }
    __syncthreads();
    if (lastf) {
        float* qs = h2s;                  // reuse (needs 1984+512 <= 4192)
        float* swp = h2s + C2N * NPOOL;
        for (int i = tid; i < C2N * NPOOL; i += 256)
            qs[i] = g_q[b * C2N * NPOOL + i];
        for (int i = tid; i < C2N * PWN; i += 256)
            swp[i] = sepw[i];
        __syncthreads();

        const int j  = tid & 15;
        const int e0 = tid >> 4;
        for (int r = 0; r < 6; ++r) {
            int e  = e0 + r * 16;         // 0..95 = c2*3 + to
            int c2 = e / 3, to = e % 3;
            int t  = to * PWN + j;
            float y = sepb[c2];
            #pragma unroll
            for (int u = 0; u < PWN; ++u) {
                int tq = t - 7 + u;
                if (tq >= 0 && tq < NPOOL)
                    y = fmaf(swp[c2 * PWN + u], qs[c2 * NPOOL + tq], y);
            }
            float s3  = g3[c2] * rsqrtf(v3[c2] + EPSF);
            float sh3 = bb3[c2] - m3[c2] * s3;
            float yb = y * s3 + sh3;
            float v = yb > 0.f ? yb : expm1f(yb);
            #pragma unroll
            for (int o = 8; o > 0; o >>= 1)
                v += __shfl_down_sync(0xffffffffu, v, o, 16);
            if (j == 0) out[b * (C2N * 3) + e] = v * (1.f / PWN);
        }
        __syncthreads();
        if (tid == 0) atomicExch(&g_cnt[b], 0);   // reset for graph replays
    }
}

// ============================================================
extern "C" void kernel_launch(void* const* d_in, const int* in_sizes, int n_in,
                              void* d_out, int out_size)
{
    const float* x     = (const float*)d_in[0];
    const float* ahat  = (const float*)d_in[1];
    const float* w1    = (const float*)d_in[2];
    const float* b1c   = (const float*)d_in[3];
    const float* g1    = (const float*)d_in[4];
    const float* bb1   = (const float*)d_in[5];
    const float* m1    = (const float*)d_in[6];
    const float* v1    = (const float*)d_in[7];
    const float* gcw   = (const float*)d_in[8];
    const float* gcb   = (const float*)d_in[9];
    const float* dww   = (const float*)d_in[10];
    const float* dwb   = (const float*)d_in[11];
    const float* g2    = (const float*)d_in[12];
    const float* bb2   = (const float*)d_in[13];
    const float* m2    = (const float*)d_in[14];
    const float* v2    = (const float*)d_in[15];
    const float* caw1  = (const float*)d_in[16];
    const float* cab1  = (const float*)d_in[17];
    const float* caw2  = (const float*)d_in[18];
    const float* cab2  = (const float*)d_in[19];
    const float* saw   = (const float*)d_in[20];
    const float* sag   = (const float*)d_in[21];
    const float* sab   = (const float*)d_in[22];
    const float* sam   = (const float*)d_in[23];
    const float* sav   = (const float*)d_in[24];
    const float* sepw  = (const float*)d_in[25];
    const float* sepb  = (const float*)d_in[26];
    const float* g3    = (const float*)d_in[27];
    const float* bb3   = (const float*)d_in[28];
    const float* m3    = (const float*)d_in[29];
    const float* v3    = (const float*)d_in[30];

    cudaFuncSetAttribute(k1_front, cudaFuncAttributeMaxDynamicSharedMemorySize,
                         SMEM_BYTES);

    dim3 grid1(NTILE, BB);
    k1_front<<<grid1, 1024, SMEM_BYTES>>>(x, ahat, w1, b1c, g1, bb1, m1, v1,
                                          gcw, gcb, dww, dwb, g2, bb2, m2, v2);

    dim3 grid2b(NTILE2, BB);
    k2b_attpool<<<grid2b, 256>>>(caw1, cab1, caw2, cab2, saw, sag, sab, sam, sav,
                                 sepw, sepb, g3, bb3, m3, v3, (float*)d_out);
}

// round 16
// speedup vs baseline: 1.3300x; 1.0123x over previous
#include <cuda_runtime.h>
#include <math.h>

// ---------------- problem constants ----------------
#define BB     16
#define F1N    16
#define CC     64
#define TTOT   1000
#define KK     64
#define C2N    32
#define PWN    16
#define EPSF   1e-5f

// ---------------- kernel-1 tiling ----------------
#define TILE   112         // time points per block
#define NTILE  9           // 9*112 = 1008 >= 1000 (last tile partial)
#define TSUB   16          // chunk of t per phase round
#define NCHUNK 7           // 7*16 = 112
#define XS_W   177         // TILE + 63 halo + 2 (odd -> conflict-free)
#define ES_S   17          // es row stride (odd -> conflict-free)

// smem float counts
#define NF_XS   (CC*XS_W)       // 11328
#define NF_WS   (F1N*KK)        // 1024
#define NF_AH   (CC*CC)         // 4096 (reused as xg/ps double buffers)
#define NF_DW   (C2N*CC)        // 2048
#define NF_ES1  (F1N*CC*ES_S)   // 17408 (one buffer)
#define NF_M0   (C2N*CC)        // 2048
#define NF_SMALL 144
#define SMEM_FLOATS (NF_XS+NF_WS+NF_AH+NF_DW+2*NF_ES1+NF_M0+NF_SMALL)
#define SMEM_BYTES  (SMEM_FLOATS*4)   // ~222 KB <= 232448 cap

// K2 tiling
#define K2B_W    8
#define K2B_T    (K2B_W*PWN)  // 128
#define NTILE2   8
#define NPOOL    62

__device__ float g_h2[BB * C2N * TTOT];
__device__ float g_psum[BB * C2N * NTILE];
__device__ float g_pmax[BB * C2N * NTILE];
__device__ float g_q[BB * C2N * NPOOL];

__device__ __forceinline__ float eluf(float v) {
    return v > 0.f ? v : (__expf(v) - 1.f);   // MUFU exp; err ~2e-7
}

#define BAR_SYNC(id, cnt)   asm volatile("bar.sync %0, %1;"   :: "r"(id), "r"(cnt) : "memory")
#define BAR_ARRIVE(id, cnt) asm volatile("bar.arrive %0, %1;" :: "r"(id), "r"(cnt) : "memory")

// ============================================================
// Kernel 1: warp-specialized producer/consumer with split prologue.
//  warps 0-15 : stage xs/ws -> temporal conv (2 filters/window) -> es[p]
//  warps 16-31: stage ah/dw -> M0 -> GCN/expansion/BN2 -> g_h2 + stats
// grid (NTILE, BB) = 144 blocks, 1024 threads
// ============================================================
__global__ void __launch_bounds__(1024, 1)
k1_front(const float* __restrict__ x,
         const float* __restrict__ ahat_g,
         const float* __restrict__ w1,  const float* __restrict__ b1c,
         const float* __restrict__ g1,  const float* __restrict__ bb1,
         const float* __restrict__ m1,  const float* __restrict__ v1,
         const float* __restrict__ gcw, const float* __restrict__ gcb,
         const float* __restrict__ dww_g, const float* __restrict__ dwb,
         const float* __restrict__ g2,  const float* __restrict__ bb2,
         const float* __restrict__ m2,  const float* __restrict__ v2)
{
    extern __shared__ float sm[];
    float* xs  = sm;                 // [CC][XS_W]
    float* ws  = xs  + NF_XS;        // [F1][KK] (BN1-scaled weights)
    float* ah  = ws  + NF_WS;        // [CC][CC]; later xg/ps parity buffers
    float* dw  = ah  + NF_AH;        // [C2][CC] (16B aligned)
    float* es0 = dw  + NF_DW;        // [F1][CC][ES_S] buffer 0
    float* es1 = es0 + NF_ES1;       // buffer 1
    float* m0  = es1 + NF_ES1;       // [C2][CC] (16B aligned)
    float* o1s = m0  + NF_M0;        // [F1]
    float* s2  = o1s + F1N + F1N;    // [C2]
    float* sh2 = s2  + C2N;          // [C2]
    float* cst = sh2 + C2N;          // [C2]

    const int tid = threadIdx.x;
    const int b   = blockIdx.y;
    const int t0  = blockIdx.x * TILE;

    if (tid < 512) {
        // ================= CONV PRODUCER (warps 0-15) =================
        for (int i = tid; i < NF_XS; i += 512) {
            int c = i / XS_W, j = i % XS_W;
            int tg = t0 - 31 + j;
            xs[i] = (tg >= 0 && tg < TTOT) ? x[(b * CC + c) * TTOT + tg] : 0.f;
        }
        for (int i = tid; i < NF_WS; i += 512) {
            int f = i / KK;
            float s1 = g1[f] * rsqrtf(v1[f] + EPSF);
            ws[i] = w1[i] * s1;
        }
        if (tid < F1N) {
            float s1 = g1[tid] * rsqrtf(v1[tid] + EPSF);
            o1s[tid] = b1c[tid] * s1 + bb1[tid] - m1[tid] * s1;
        }
        BAR_SYNC(1, 512);            // producer staging complete

        const int fpair = tid >> 6;  // 0..7; computes filters fpair, fpair+8
        const int c     = tid & 63;
        const float* xrow = xs + c * XS_W;
        const float* wr0 = ws + fpair * KK;
        const float* wr1 = ws + (fpair + 8) * KK;
        const float o0 = o1s[fpair], o1v = o1s[fpair + 8];

        for (int chk = 0; chk < NCHUNK; ++chk) {
            const int p  = chk & 1;
            const int ct = chk * TSUB;
            float* esb = p ? es1 : es0;
            if (chk >= 2) BAR_SYNC(4 + p, 1024);   // wait es[p] consumed

            float acc0[TSUB], acc1[TSUB], win[TSUB];
            #pragma unroll
            for (int i = 0; i < TSUB; ++i) {
                acc0[i] = acc1[i] = 0.f;
                win[i] = xrow[ct + i];
            }
            int k = 0;
            #pragma unroll 1
            for (int m = 0; m < 4; ++m) {
                #pragma unroll
                for (int kk = 0; kk < 16; ++kk) {
                    float w0 = wr0[k + kk], w1v = wr1[k + kk];
                    #pragma unroll
                    for (int i = 0; i < TSUB; ++i) {
                        float xv = win[(kk + i) & 15];
                        acc0[i] = fmaf(w0, xv, acc0[i]);
                        acc1[i] = fmaf(w1v, xv, acc1[i]);
                    }
                    win[kk] = xrow[ct + k + kk + TSUB];
                }
                k += 16;
            }
            float* e0 = esb + (fpair * CC + c) * ES_S;
            float* e1 = esb + ((fpair + 8) * CC + c) * ES_S;
            #pragma unroll
            for (int i = 0; i < TSUB; ++i) {
                e0[i] = eluf(acc0[i] + o0);
                e1[i] = eluf(acc1[i] + o1v);
            }
            __threadfence_block();
            BAR_ARRIVE(2 + p, 1024);               // signal es[p] full
        }
    } else {
        // ================= PHASE CONSUMER (warps 16-31) =================
        const int tl  = tid - 512;        // 0..511
        const int c2  = tl >> 4;
        const int tt  = tl & 15;
        const int ff  = c2 >> 1;

        for (int i = tl; i < NF_AH; i += 512) ah[i] = ahat_g[i];
        for (int i = tl; i < NF_DW; i += 512) dw[i] = dww_g[i];
        if (tl < C2N) {
            float s = g2[tl] * rsqrtf(v2[tl] + EPSF);
            s2[tl]  = s;
            sh2[tl] = bb2[tl] - m2[tl] * s;
        }
        BAR_SYNC(7, 512);            // ah/dw loaded
        if (tl < C2N) {
            float wsum = 0.f;
            for (int c = 0; c < CC; ++c) wsum += dw[tl * CC + c];
            cst[tl] = gcb[tl >> 1] * wsum + dwb[tl];
        }
        for (int it = tl; it < C2N * CC; it += 512) {
            int cq = it >> 6, j = it & 63;
            const float* dr = dw + cq * CC;
            float s = 0.f;
            #pragma unroll 8
            for (int cc = 0; cc < CC; ++cc)
                s = fmaf(dr[cc], ah[cc * CC + j], s);
            m0[it] = s * gcw[cq >> 1] * (1.f / F1N);
        }
        BAR_SYNC(7, 512);            // M0 done; ah region now reusable

        float stat_s = 0.f, stat_m = -INFINITY;

        for (int chk = 0; chk < NCHUNK; ++chk) {
            const int p = chk & 1;
            const float* esb = p ? es1 : es0;
            float* xgb = ah + p * 2048;            // [CC*TSUB] = 1024
            float* psb = xgb + 1024;               // [C2*TSUB] = 512
            BAR_SYNC(2 + p, 1024);                 // wait es[p] full

            #pragma unroll
            for (int r = 0; r < 2; ++r) {
                int item = tl + r * 512;
                int cc = item >> 4, tti = item & 15;
                const float* er = esb + cc * ES_S + tti;
                float s = 0.f;
                #pragma unroll
                for (int f2 = 0; f2 < F1N; ++f2)
                    s += er[f2 * CC * ES_S];
                xgb[item] = s;                     // raw sum (M0 holds /F1)
            }
            {
                const float4* dr4 = (const float4*)(dw + c2 * CC);
                const float* er = esb + ff * CC * ES_S + tt;
                float s = 0.f;
                #pragma unroll
                for (int q = 0; q < 16; ++q) {
                    float4 d = dr4[q];
                    int cc = q * 4;
                    s = fmaf(d.x, er[(cc + 0) * ES_S], s);
                    s = fmaf(d.y, er[(cc + 1) * ES_S], s);
                    s = fmaf(d.z, er[(cc + 2) * ES_S], s);
                    s = fmaf(d.w, er[(cc + 3) * ES_S], s);
                }
                psb[tl] = s;
            }
            BAR_SYNC(6, 512);                      // es reads + xg writes done
            BAR_ARRIVE(4 + p, 1024);               // conv may overwrite es[p]

            {
                const float4* mr4 = (const float4*)(m0 + c2 * CC);
                const float* xr = xgb + tt;
                float s = psb[tl];
                #pragma unroll
                for (int q = 0; q < 16; ++q) {
                    float4 m = mr4[q];
                    int j = q * 4;
                    s = fmaf(m.x, xr[(j + 0) * TSUB], s);
                    s = fmaf(m.y, xr[(j + 1) * TSUB], s);
                    s = fmaf(m.z, xr[(j + 2) * TSUB], s);
                    s = fmaf(m.w, xr[(j + 3) * TSUB], s);
                }
                float outv = (s + cst[c2]) * s2[c2] + sh2[c2];
                int t = t0 + chk * TSUB + tt;
                bool valid = (t < TTOT);
                if (valid) g_h2[(b * C2N + c2) * TTOT + t] = outv;
                float sv = valid ? outv : 0.f;
                float mv = valid ? outv : -INFINITY;
                #pragma unroll
                for (int o = 8; o > 0; o >>= 1) {
                    sv += __shfl_down_sync(0xffffffffu, sv, o, 16);
                    mv  = fmaxf(mv, __shfl_down_sync(0xffffffffu, mv, o, 16));
                }
                if (tt == 0) { stat_s += sv; stat_m = fmaxf(stat_m, mv); }
            }
        }

        if (tt == 0) {
            g_psum[(b * C2N + c2) * NTILE + blockIdx.x] = stat_s;
            g_pmax[(b * C2N + c2) * NTILE + blockIdx.x] = stat_m;
        }
    }
}

// ============================================================
// Kernel 2b: channel attn + spatial attn + ELU + pool16 -> g_q
// grid (NTILE2, BB), 256 threads; float4 g_h2 loads
// ============================================================
#define H2S_S 131
__global__ void __launch_bounds__(256, 4)
k2b_attpool(const float* __restrict__ caw1, const float* __restrict__ cab1,
            const float* __restrict__ caw2, const float* __restrict__ cab2,
            const float* __restrict__ saw,
            const float* __restrict__ sag, const float* __restrict__ sab,
            const float* __restrict__ sam, const float* __restrict__ sav)
{
    __shared__ float att[C2N];
    __shared__ float h2s[C2N * H2S_S];
    __shared__ float mms[K2B_T + 2], mxs[K2B_T + 2], sgs[K2B_T];
    __shared__ float sstat[C2N];

    const int tile = blockIdx.x, b = blockIdx.y;
    const int tid  = threadIdx.x;
    const int t0   = tile * K2B_T;
    const int tw   = (tile == NTILE2 - 1) ? (NPOOL * PWN - t0) : K2B_T;
    const int nw   = tw / PWN;
    const int nv   = tw >> 2;          // float4 count per row (32 or 24)

    if (tid < C2N) {
        float s = 0.f, m = -INFINITY;
        const float* pss = g_psum + (b * C2N + tid) * NTILE;
        const float* pm = g_pmax + (b * C2N + tid) * NTILE;
        #pragma unroll
        for (int tl = 0; tl < NTILE; ++tl) {
            s += pss[tl]; m = fmaxf(m, pm[tl]);
        }
        sstat[tid] = s * (1.f / TTOT) + m;
    }
    __syncthreads();
    if (tid < C2N) {
        float r0 = cab1[0], r1 = cab1[1];
        for (int j = 0; j < C2N; ++j) {
            r0 += caw1[j] * sstat[j];
            r1 += caw1[C2N + j] * sstat[j];
        }
        r0 = fmaxf(r0, 0.f); r1 = fmaxf(r1, 0.f);
        float z = cab2[tid] + caw2[tid * 2] * r0 + caw2[tid * 2 + 1] * r1;
        att[tid] = 1.f / (1.f + expf(-z));
    }
    __syncthreads();

    const float* h2 = g_h2 + b * C2N * TTOT;
    // body: vectorized LDG.128 (c2*TTOT + t0 is 4-elem aligned)
    for (int it = tid; it < C2N * nv; it += 256) {
        int c2 = it / nv, jj = it % nv;
        float4 v = *(const float4*)(h2 + c2 * TTOT + t0 + 4 * jj);
        float a = att[c2];
        float* d = h2s + c2 * H2S_S + 1 + 4 * jj;
        d[0] = v.x * a; d[1] = v.y * a; d[2] = v.z * a; d[3] = v.w * a;
    }
    // halo: t0-1 and t0+tw
    if (tid < 64) {
        int c2 = tid >> 1, side = tid & 1;
        int t = side ? (t0 + tw) : (t0 - 1);
        float v = (t >= 0 && t < TTOT) ? h2[c2 * TTOT + t] * att[c2] : 0.f;
        h2s[c2 * H2S_S + (side ? tw + 1 : 0)] = v;
    }
    __syncthreads();

    for (int j = tid; j < tw + 2; j += 256) {
        float s = 0.f, mx = -INFINITY;
        #pragma unroll 8
        for (int c2 = 0; c2 < C2N; ++c2) {
            float v = h2s[c2 * H2S_S + j];
            s += v; mx = fmaxf(mx, v);
        }
        mms[j] = s * (1.f / C2N);
        mxs[j] = mx;
    }
    __syncthreads();

    {
        float ssa = sag[0] * rsqrtf(sav[0] + EPSF);
        float sha = sab[0] - sam[0] * ssa;
        for (int j = tid; j < tw; j += 256) {
            int t = t0 + j;
            float acc = 0.f;
            #pragma unroll
            for (int kw = 0; kw < 3; ++kw) {
                int tt = t - 1 + kw;
                if (tt >= 0 && tt < TTOT)
                    acc += saw[3 + kw] * mms[j + kw] + saw[12 + kw] * mxs[j + kw];
            }
            float z = acc * ssa + sha;
            sgs[j] = 1.f / (1.f + expf(-z));
        }
    }
    __syncthreads();

    {
        int c2 = tid & 31, w = tid >> 5;
        if (w < nw) {
            float acc = 0.f;
            #pragma unroll
            for (int j = 0; j < PWN; ++j) {
                int tl = w * PWN + j;
                float v = h2s[c2 * H2S_S + tl + 1] * sgs[tl];
                acc += (v > 0.f ? v : expm1f(v));
            }
            g_q[(b * C2N + c2) * NPOOL + tile * K2B_W + w] = acc * (1.f / PWN);
        }
    }
}

// ============================================================
// Kernel 2c: depthwise sep conv + BN3 + ELU + pool16 -> out
// grid (BB), 256 threads
// ============================================================
__global__ void __launch_bounds__(256, 4)
k2c_tail(const float* __restrict__ sepw, const float* __restrict__ sepb,
         const float* __restrict__ g3, const float* __restrict__ bb3,
         const float* __restrict__ m3, const float* __restrict__ v3,
         float* __restrict__ out)
{
    __shared__ float qs[C2N * NPOOL];
    __shared__ float sw[C2N * PWN];
    const int b = blockIdx.x, tid = threadIdx.x;
    for (int i = tid; i < C2N * NPOOL; i += 256)
        qs[i] = g_q[b * C2N * NPOOL + i];
    for (int i = tid; i < C2N * PWN; i += 256)
        sw[i] = sepw[i];
    __syncthreads();

    const int j  = tid & 15;
    const int e0 = tid >> 4;
    for (int r = 0; r < 6; ++r) {
        int e  = e0 + r * 16;          // 0..95 = c2*3 + to
        int c2 = e / 3, to = e % 3;
        int t  = to * PWN + j;
        float y = sepb[c2];
        #pragma unroll
        for (int u = 0; u < PWN; ++u) {
            int tq = t - 7 + u;
            if (tq >= 0 && tq < NPOOL) y = fmaf(sw[c2 * PWN + u], qs[c2 * NPOOL + tq], y);
        }
        float s3  = g3[c2] * rsqrtf(v3[c2] + EPSF);
        float sh3 = bb3[c2] - m3[c2] * s3;
        float yb = y * s3 + sh3;
        float v = yb > 0.f ? yb : expm1f(yb);
        #pragma unroll
        for (int o = 8; o > 0; o >>= 1)
            v += __shfl_down_sync(0xffffffffu, v, o, 16);
        if (j == 0) out[b * (C2N * 3) + e] = v * (1.f / PWN);
    }
}

// ============================================================
extern "C" void kernel_launch(void* const* d_in, const int* in_sizes, int n_in,
                              void* d_out, int out_size)
{
    const float* x     = (const float*)d_in[0];
    const float* ahat  = (const float*)d_in[1];
    const float* w1    = (const float*)d_in[2];
    const float* b1c   = (const float*)d_in[3];
    const float* g1    = (const float*)d_in[4];
    const float* bb1   = (const float*)d_in[5];
    const float* m1    = (const float*)d_in[6];
    const float* v1    = (const float*)d_in[7];
    const float* gcw   = (const float*)d_in[8];
    const float* gcb   = (const float*)d_in[9];
    const float* dww   = (const float*)d_in[10];
    const float* dwb   = (const float*)d_in[11];
    const float* g2    = (const float*)d_in[12];
    const float* bb2   = (const float*)d_in[13];
    const float* m2    = (const float*)d_in[14];
    const float* v2    = (const float*)d_in[15];
    const float* caw1  = (const float*)d_in[16];
    const float* cab1  = (const float*)d_in[17];
    const float* caw2  = (const float*)d_in[18];
    const float* cab2  = (const float*)d_in[19];
    const float* saw   = (const float*)d_in[20];
    const float* sag   = (const float*)d_in[21];
    const float* sab   = (const float*)d_in[22];
    const float* sam   = (const float*)d_in[23];
    const float* sav   = (const float*)d_in[24];
    const float* sepw  = (const float*)d_in[25];
    const float* sepb  = (const float*)d_in[26];
    const float* g3    = (const float*)d_in[27];
    const float* bb3   = (const float*)d_in[28];
    const float* m3    = (const float*)d_in[29];
    const float* v3    = (const float*)d_in[30];

    cudaFuncSetAttribute(k1_front, cudaFuncAttributeMaxDynamicSharedMemorySize,
                         SMEM_BYTES);

    dim3 grid1(NTILE, BB);
    k1_front<<<grid1, 1024, SMEM_BYTES>>>(x, ahat, w1, b1c, g1, bb1, m1, v1,
                                          gcw, gcb, dww, dwb, g2, bb2, m2, v2);

    dim3 grid2b(NTILE2, BB);
    k2b_attpool<<<grid2b, 256>>>(caw1, cab1, caw2, cab2, saw, sag, sab, sam, sav);

    k2c_tail<<<BB, 256>>>(sepw, sepb, g3, bb3, m3, v3, (float*)d_out);
}